// round 13
// baseline (speedup 1.0000x reference)
#include <cuda_runtime.h>
#include <cuda_fp16.h>
#include <cstdint>

// ===========================================================================
// BiMamba with int8 IMMA 3-product GEMMs (in_proj / out_proj / merge):
//   X ≈ s * (128*Xh + Xl)  (Xh, Xl int8; per-row scale s = amax/16256)
//   C = sa*sb*(16384*acc1 + 128*acc2),  acc1=sum(AhBh), acc2=sum(AhBl+AlBh)
// dt projection stays fp16 2-product (K=64). 3-stage cp.async pipeline.
// B=2, L=1024, D_MODEL=1024, D_INNER=2048, DT_RANK=64, D_STATE=16
// ===========================================================================

#define BSZ     2
#define SEQ     1024
#define DMODEL  1024
#define DINNER  2048
#define DTRANK  64
#define DSTATE  16
#define TOK     (BSZ*SEQ)

#define PLANE_XZ   ((size_t)TOK * (2*DINNER))
#define PLANE_E    ((size_t)TOK * DINNER)
#define PLANE_DBL  ((size_t)TOK * 96)

// fp32 intermediates
__device__ float g_xz[2][PLANE_XZ];     // xi | z per direction
__device__ float g_xc[2][PLANE_E];      // conv+silu output
__device__ float g_dbl[2][PLANE_DBL];   // dt(64) | B(16) | C(16)
__device__ float g_delta[2][PLANE_E];   // softplus(dt@dt_w + b)
__device__ float g_y[2][PLANE_E];       // scan output (fp32)
__device__ float g_ocatf[PLANE_E];      // [2048][2048] fwd | flip(bwd) fp32

// int8 quantized operands (rows packed [hi(K) | lo(K)] bytes)
__device__ int8_t q_x   [(size_t)TOK * 2*DMODEL];
__device__ int8_t q_win [2][(size_t)2*DINNER * 2*DMODEL];
__device__ int8_t q_wop [2][(size_t)DMODEL * 2*DINNER];
__device__ int8_t q_wmg [(size_t)DMODEL * 2*(2*DMODEL)];
__device__ int8_t q_y   [2][(size_t)TOK * 2*DINNER];
__device__ int8_t q_ocat[(size_t)TOK * 2*(2*DMODEL)];
// per-row scales
__device__ float s_x[TOK];
__device__ float s_win[2][2*DINNER];
__device__ float s_wop[2][DMODEL];
__device__ float s_wmg[DMODEL];
__device__ float s_y[2][TOK];
__device__ float s_ocat[TOK];

// fp16 operands for dt projection
__device__ __half g_wdt [2][(size_t)DINNER * DTRANK];
__device__ __half g_dthl[2][(size_t)TOK * 2*DTRANK];

// ---------------------------------------------------------------------------
// asm helpers
// ---------------------------------------------------------------------------
__device__ __forceinline__ void ldsm_x4(uint32_t* r, uint32_t addr) {
    asm volatile("ldmatrix.sync.aligned.m8n8.x4.shared.b16 {%0,%1,%2,%3}, [%4];"
        : "=r"(r[0]), "=r"(r[1]), "=r"(r[2]), "=r"(r[3]) : "r"(addr));
}
__device__ __forceinline__ void mma16816(float* c, const uint32_t* a, const uint32_t* b) {
    asm volatile(
        "mma.sync.aligned.m16n8k16.row.col.f32.f16.f16.f32 "
        "{%0,%1,%2,%3}, {%4,%5,%6,%7}, {%8,%9}, {%0,%1,%2,%3};"
        : "+f"(c[0]), "+f"(c[1]), "+f"(c[2]), "+f"(c[3])
        : "r"(a[0]), "r"(a[1]), "r"(a[2]), "r"(a[3]), "r"(b[0]), "r"(b[1]));
}
__device__ __forceinline__ void mma16832i(int* c, const uint32_t* a, const uint32_t* b) {
    asm volatile(
        "mma.sync.aligned.m16n8k32.row.col.s32.s8.s8.s32 "
        "{%0,%1,%2,%3}, {%4,%5,%6,%7}, {%8,%9}, {%0,%1,%2,%3};"
        : "+r"(c[0]), "+r"(c[1]), "+r"(c[2]), "+r"(c[3])
        : "r"(a[0]), "r"(a[1]), "r"(a[2]), "r"(a[3]), "r"(b[0]), "r"(b[1]));
}
#define CP_ASYNC16(dst, src) \
    asm volatile("cp.async.cg.shared.global [%0], [%1], 16;" :: "r"(dst), "l"(src))
#define CP_COMMIT() asm volatile("cp.async.commit_group;" ::: "memory")
#define CP_WAIT1()  asm volatile("cp.async.wait_group 1;" ::: "memory")
#define CP_WAIT0()  asm volatile("cp.async.wait_group 0;" ::: "memory")

#define GSMEM (3*32768)

// ---------------------------------------------------------------------------
// int8 3-product GEMM. Block tile 128x128, BK=128 bytes, 3-stage ring,
// 8 warps (2x4). A rows [hi(K)|lo(K)] bytes, B rows likewise.
// Virtual chunks: nk hh -> acc1, nk hl + nk lh -> acc2.
// ---------------------------------------------------------------------------
__global__ __launch_bounds__(256)
void gemm_i8(const int8_t* __restrict__ A0, const int8_t* __restrict__ A1,
             const int8_t* __restrict__ B0, const int8_t* __restrict__ B1,
             const float* __restrict__ sa0, const float* __restrict__ sa1,
             const float* __restrict__ sb0, const float* __restrict__ sb1,
             float* C0, float* C1, int ldc,
             int K, int flipa0, int flipa1, int flipc0, int flipc1)
{
    extern __shared__ __align__(128) char smem_raw[];
    const uint32_t sbase = (uint32_t)__cvta_generic_to_shared(smem_raw);

    const int z = blockIdx.z;
    const int8_t* A = z ? A1 : A0;
    const int8_t* B = z ? B1 : B0;
    const float* sa = z ? sa1 : sa0;
    const float* sb = z ? sb1 : sb0;
    float* C = z ? C1 : C0;
    const int flipa = z ? flipa1 : flipa0;
    const int flipc = z ? flipc1 : flipc0;

    const int tid = threadIdx.x;
    const int wid = tid >> 5;
    const int lid = tid & 31;
    const int bm = blockIdx.y * 128;
    const int bn = blockIdx.x * 128;

    const int wm = wid >> 2;
    const int wn = wid & 3;
    const int mbase = wm * 64;
    const int nbase = wn * 32;

    const int qrow = lid & 15;
    const int qc16 = lid >> 4;

    const int lda2 = 2 * K;            // bytes per row
    const int nk = K >> 7;             // 128-byte chunks
    const int nv = 3 * nk;

    int acc1[4][4][4], acc2[4][4][4];
#pragma unroll
    for (int f = 0; f < 4; f++)
#pragma unroll
        for (int g = 0; g < 4; g++)
#pragma unroll
            for (int e = 0; e < 4; e++) { acc1[f][g][e] = 0; acc2[f][g][e] = 0; }

    auto sA = [&](int st) -> uint32_t { return sbase + (uint32_t)st * 32768u; };
    auto sB = [&](int st) -> uint32_t { return sbase + (uint32_t)st * 32768u + 16384u; };

    auto load_stage = [&](int v, int st) {
        int aoff, boff;
        if (v < nk)          { aoff = v << 7;                boff = v << 7; }
        else if (v < 2*nk)   { aoff = (v - nk) << 7;         boff = K + ((v - nk) << 7); }
        else                 { aoff = K + ((v - 2*nk) << 7); boff = (v - 2*nk) << 7; }
        uint32_t da = sA(st), db = sB(st);
#pragma unroll
        for (int i = 0; i < 4; i++) {
            int ch  = tid + (i << 8);
            int r   = ch >> 3;
            int c16 = ch & 7;
            uint32_t sw = (uint32_t)((c16 ^ (r & 7)) << 4) + (uint32_t)(r << 7);
            int gm = bm + r;
            int am = flipa ? (gm ^ (SEQ-1)) : gm;
            CP_ASYNC16(da + sw, A + (size_t)am * lda2 + aoff + (c16 << 4));
            CP_ASYNC16(db + sw, B + (size_t)(bn + r) * lda2 + boff + (c16 << 4));
        }
    };

    auto compute_stage = [&](int st, int (&acc)[4][4][4]) {
        uint32_t sa_ = sA(st), sb_ = sB(st);
#pragma unroll
        for (int s = 0; s < 4; s++) {            // 32 bytes of K per step
            uint32_t bq[2][4];
#pragma unroll
            for (int g2 = 0; g2 < 2; g2++) {
                int r = nbase + g2*16 + qrow;
                int c = (s << 1) + qc16;
                ldsm_x4(bq[g2], sb_ + (uint32_t)(r << 7) + (uint32_t)((c ^ (r & 7)) << 4));
            }
#pragma unroll
            for (int f = 0; f < 4; f++) {
                int r = mbase + f*16 + qrow;
                int c = (s << 1) + qc16;
                uint32_t afr[4];
                ldsm_x4(afr, sa_ + (uint32_t)(r << 7) + (uint32_t)((c ^ (r & 7)) << 4));
#pragma unroll
                for (int g = 0; g < 4; g++) {
                    uint32_t bfr[2] = { bq[g >> 1][g & 1], bq[g >> 1][(g & 1) + 2] };
                    mma16832i(acc[f][g], afr, bfr);
                }
            }
        }
    };

    load_stage(0, 0); CP_COMMIT();
    if (nv > 1) { load_stage(1, 1); CP_COMMIT(); }

    for (int v = 0; v < nv; v++) {
        int st = v % 3;
        if (v < nv - 1) CP_WAIT1(); else CP_WAIT0();
        __syncthreads();
        if (v < nk) compute_stage(st, acc1);
        else        compute_stage(st, acc2);
        int vn = v + 2;
        if (vn < nv) { load_stage(vn, vn % 3); CP_COMMIT(); }
    }

    // ---- epilogue: dequant + write fp32 ----
    const int crow = lid >> 2;
    const int ccol = (lid & 3) * 2;
#pragma unroll
    for (int f = 0; f < 4; f++) {
        int m0 = bm + mbase + f*16 + crow;
        int m1 = m0 + 8;
        int ar0 = flipa ? (m0 ^ (SEQ-1)) : m0;   // A physical row (scale idx)
        int ar1 = flipa ? (m1 ^ (SEQ-1)) : m1;
        int wr0 = flipc ? (m0 ^ (SEQ-1)) : m0;   // C write row
        int wr1 = flipc ? (m1 ^ (SEQ-1)) : m1;
        float sav0 = sa[ar0], sav1 = sa[ar1];
#pragma unroll
        for (int g = 0; g < 4; g++) {
            int n = bn + nbase + g*8 + ccol;
            float sb0v = sb[n], sb1v = sb[n+1];
            float v0 = sav0*sb0v*(16384.f*(float)acc1[f][g][0] + 128.f*(float)acc2[f][g][0]);
            float v1 = sav0*sb1v*(16384.f*(float)acc1[f][g][1] + 128.f*(float)acc2[f][g][1]);
            float v2 = sav1*sb0v*(16384.f*(float)acc1[f][g][2] + 128.f*(float)acc2[f][g][2]);
            float v3 = sav1*sb1v*(16384.f*(float)acc1[f][g][3] + 128.f*(float)acc2[f][g][3]);
            *reinterpret_cast<float2*>(C + (size_t)wr0*ldc + n) = make_float2(v0, v1);
            *reinterpret_cast<float2*>(C + (size_t)wr1*ldc + n) = make_float2(v2, v3);
        }
    }
}

// ---------------------------------------------------------------------------
// Row-wise int8 hi/lo quantizer: out rows [hi(K)|lo(K)], scale[r]=amax/16256.
// One block (256 thr) per row; K multiple of 4, K <= 8192.
// ---------------------------------------------------------------------------
__global__ __launch_bounds__(256)
void quant_rows(const float* __restrict__ in, int8_t* __restrict__ out,
                float* __restrict__ scale, int K)
{
    const int row = blockIdx.x;
    const float* src = in + (size_t)row * K;
    __shared__ float red[256];

    float am = 0.f;
    for (int i = threadIdx.x * 4; i < K; i += 1024) {
        float4 v = *reinterpret_cast<const float4*>(src + i);
        am = fmaxf(am, fmaxf(fmaxf(fabsf(v.x), fabsf(v.y)),
                             fmaxf(fabsf(v.z), fabsf(v.w))));
    }
    red[threadIdx.x] = am;
    __syncthreads();
    for (int s = 128; s > 0; s >>= 1) {
        if (threadIdx.x < s) red[threadIdx.x] = fmaxf(red[threadIdx.x], red[threadIdx.x + s]);
        __syncthreads();
    }
    float amax = fmaxf(red[0], 1e-20f);
    if (threadIdx.x == 0) scale[row] = amax / 16256.f;
    const float inv = 16256.f / amax;

    int8_t* oh = out + (size_t)row * 2 * K;
    int8_t* ol = oh + K;
    for (int i = threadIdx.x * 4; i < K; i += 1024) {
        float4 v = *reinterpret_cast<const float4*>(src + i);
        char4 ch, cl;
        {
            float xq = v.x * inv; float ah = rintf(xq * 0.0078125f);
            ch.x = (int8_t)(int)ah; cl.x = (int8_t)(int)rintf(xq - 128.f*ah);
        }
        {
            float xq = v.y * inv; float ah = rintf(xq * 0.0078125f);
            ch.y = (int8_t)(int)ah; cl.y = (int8_t)(int)rintf(xq - 128.f*ah);
        }
        {
            float xq = v.z * inv; float ah = rintf(xq * 0.0078125f);
            ch.z = (int8_t)(int)ah; cl.z = (int8_t)(int)rintf(xq - 128.f*ah);
        }
        {
            float xq = v.w * inv; float ah = rintf(xq * 0.0078125f);
            ch.w = (int8_t)(int)ah; cl.w = (int8_t)(int)rintf(xq - 128.f*ah);
        }
        *reinterpret_cast<char4*>(oh + i) = ch;
        *reinterpret_cast<char4*>(ol + i) = cl;
    }
}

// ---------------------------------------------------------------------------
// fp16 2-product GEMM (dt projection only, K=64). Same as R10.
// ---------------------------------------------------------------------------
template<bool SOFTPLUS>
__global__ __launch_bounds__(256, 2)
void gemm_f16(const __half* __restrict__ A0, const __half* __restrict__ A1,
              const __half* __restrict__ B0, const __half* __restrict__ B1,
              float* C0, float* C1, int ldc,
              int K, const float* bias0, const float* bias1)
{
    extern __shared__ __align__(128) char smem_raw[];
    const uint32_t sbase = (uint32_t)__cvta_generic_to_shared(smem_raw);

    const int z = blockIdx.z;
    const __half* A = z ? A1 : A0;
    const __half* B = z ? B1 : B0;
    float* C = z ? C1 : C0;
    const float* bias = z ? bias1 : bias0;

    const int tid = threadIdx.x;
    const int wid = tid >> 5;
    const int lid = tid & 31;
    const int bm = blockIdx.y * 128;
    const int bn = blockIdx.x * 128;

    const int wm = wid >> 2;
    const int wn = wid & 3;
    const int mbase = wm * 64;
    const int nbase = wn * 32;
    const int qrow = lid & 15;
    const int qc16 = lid >> 4;

    const int lda2 = 2 * K;
    const int nk = K >> 6;
    const int nv = 2 * nk;

    float acc[4][4][4];
#pragma unroll
    for (int f = 0; f < 4; f++)
#pragma unroll
        for (int g = 0; g < 4; g++)
#pragma unroll
            for (int e = 0; e < 4; e++) acc[f][g][e] = 0.f;

    auto sA = [&](int st) -> uint32_t { return sbase + (uint32_t)st * 32768u; };
    auto sB = [&](int st) -> uint32_t { return sbase + (uint32_t)st * 32768u + 16384u; };

    auto load_stage = [&](int v, int st) {
        int aoff, boff;
        if (v < nk) { aoff = v << 6;               boff = v << 6; }
        else        { aoff = K + ((v - nk) << 6);  boff = (v - nk) << 6; }
        uint32_t da = sA(st), db = sB(st);
#pragma unroll
        for (int i = 0; i < 4; i++) {
            int ch  = tid + (i << 8);
            int r   = ch >> 3;
            int c16 = ch & 7;
            uint32_t sw = (uint32_t)((c16 ^ (r & 7)) << 4) + (uint32_t)(r << 7);
            CP_ASYNC16(da + sw, A + (size_t)(bm + r) * lda2 + aoff + (c16 << 3));
            CP_ASYNC16(db + sw, B + (size_t)(bn + r) * K + boff + (c16 << 3));
        }
    };

    auto compute_stage = [&](int st) {
        uint32_t sa = sA(st), sb = sB(st);
#pragma unroll
        for (int s = 0; s < 4; s++) {
            uint32_t bq[2][4];
#pragma unroll
            for (int g2 = 0; g2 < 2; g2++) {
                int r = nbase + g2*16 + qrow;
                int c = (s << 1) + qc16;
                ldsm_x4(bq[g2], sb + (uint32_t)(r << 7) + (uint32_t)((c ^ (r & 7)) << 4));
            }
#pragma unroll
            for (int f = 0; f < 4; f++) {
                int r = mbase + f*16 + qrow;
                int c = (s << 1) + qc16;
                uint32_t afr[4];
                ldsm_x4(afr, sa + (uint32_t)(r << 7) + (uint32_t)((c ^ (r & 7)) << 4));
#pragma unroll
                for (int g = 0; g < 4; g++) {
                    uint32_t bfr[2] = { bq[g >> 1][g & 1], bq[g >> 1][(g & 1) + 2] };
                    mma16816(acc[f][g], afr, bfr);
                }
            }
        }
    };

    load_stage(0, 0); CP_COMMIT();
    if (nv > 1) { load_stage(1, 1); CP_COMMIT(); }
    for (int v = 0; v < nv; v++) {
        int st = v % 3;
        if (v < nv - 1) CP_WAIT1(); else CP_WAIT0();
        __syncthreads();
        compute_stage(st);
        int vn = v + 2;
        if (vn < nv) { load_stage(vn, vn % 3); CP_COMMIT(); }
    }

    const int crow = lid >> 2;
    const int ccol = (lid & 3) * 2;
#pragma unroll
    for (int f = 0; f < 4; f++) {
        int m0 = bm + mbase + f*16 + crow;
        int m1 = m0 + 8;
#pragma unroll
        for (int g = 0; g < 4; g++) {
            int n = bn + nbase + g*8 + ccol;
            float v0 = acc[f][g][0], v1 = acc[f][g][1];
            float v2 = acc[f][g][2], v3 = acc[f][g][3];
            if (SOFTPLUS) {
                float b0 = bias[n], b1 = bias[n+1];
                float x0 = v0 + b0, x1 = v1 + b1, x2 = v2 + b0, x3 = v3 + b1;
                v0 = (x0 > 20.f) ? x0 : log1pf(__expf(x0));
                v1 = (x1 > 20.f) ? x1 : log1pf(__expf(x1));
                v2 = (x2 > 20.f) ? x2 : log1pf(__expf(x2));
                v3 = (x3 > 20.f) ? x3 : log1pf(__expf(x3));
            }
            *reinterpret_cast<float2*>(C + (size_t)m0*ldc + n) = make_float2(v0, v1);
            *reinterpret_cast<float2*>(C + (size_t)m1*ldc + n) = make_float2(v2, v3);
        }
    }
}

// ---------------------------------------------------------------------------
// fp32 -> plain fp16 (dt weights)
// ---------------------------------------------------------------------------
__global__ void cvt_w(const float* __restrict__ in, __half* __restrict__ out)
{
    int idx = (blockIdx.x * blockDim.x + threadIdx.x) << 2;
    float4 v = *reinterpret_cast<const float4*>(in + idx);
    *reinterpret_cast<__half2*>(out + idx)     = __halves2half2(__float2half_rn(v.x), __float2half_rn(v.y));
    *reinterpret_cast<__half2*>(out + idx + 2) = __halves2half2(__float2half_rn(v.z), __float2half_rn(v.w));
}

// dbl (stride 96, cols 0..63) -> packed 2048 x 128 fp16 hi/lo; both dirs
__global__ void cvt_dt(const float* __restrict__ in0, __half* __restrict__ out0,
                       const float* __restrict__ in1, __half* __restrict__ out1)
{
    const float* in = blockIdx.y ? in1 : in0;
    __half* out = blockIdx.y ? out1 : out0;
    int idx = (blockIdx.x * blockDim.x + threadIdx.x) << 2;
    int row = idx >> 6;
    int col = idx & 63;
    float4 v = *reinterpret_cast<const float4*>(in + (size_t)row * 96 + col);
    __half h0 = __float2half_rn(v.x), h1 = __float2half_rn(v.y);
    __half h2 = __float2half_rn(v.z), h3 = __float2half_rn(v.w);
    __half l0 = __float2half_rn(v.x - __half2float(h0));
    __half l1 = __float2half_rn(v.y - __half2float(h1));
    __half l2 = __float2half_rn(v.z - __half2float(h2));
    __half l3 = __float2half_rn(v.w - __half2float(h3));
    size_t o = (size_t)row * 128 + col;
    *reinterpret_cast<__half2*>(out + o)          = __halves2half2(h0, h1);
    *reinterpret_cast<__half2*>(out + o + 2)      = __halves2half2(h2, h3);
    *reinterpret_cast<__half2*>(out + o + 64)     = __halves2half2(l0, l1);
    *reinterpret_cast<__half2*>(out + o + 64 + 2) = __halves2half2(l2, l3);
}

// ---------------------------------------------------------------------------
// Small split-K fp32 GEMM with atomicAdd epilogue (x_proj), both dirs (grid.z)
// ---------------------------------------------------------------------------
template<int BM,int BN,int BK,int TM,int TN>
__global__ __launch_bounds__((BM/TM)*(BN/TN))
void gemm_nt_atomic(const float* __restrict__ A0, const float* __restrict__ B0, float* C0,
                    const float* __restrict__ A1, const float* __restrict__ B1, float* C1,
                    int lda, int ldb, int ldc, int kslab)
{
    constexpr int THREADS = (BM/TM)*(BN/TN);
    __shared__ float As[BK][BM];
    __shared__ float Bs[BK][BN];
    const float* A = blockIdx.z ? A1 : A0;
    const float* B = blockIdx.z ? B1 : B0;
    float* C = blockIdx.z ? C1 : C0;
    const int tid = threadIdx.x;
    const int bm  = blockIdx.y * BM;
    const int k_lo = blockIdx.x * kslab;
    const int tx = tid % (BN/TN);
    const int ty = tid / (BN/TN);

    float acc[TM][TN];
#pragma unroll
    for (int i = 0; i < TM; i++)
#pragma unroll
        for (int j = 0; j < TN; j++) acc[i][j] = 0.f;

    constexpr int A4 = BM*BK/4;
    constexpr int B4 = BN*BK/4;
    for (int k0 = k_lo; k0 < k_lo + kslab; k0 += BK) {
        for (int i = tid; i < A4; i += THREADS) {
            int r  = i / (BK/4);
            int kq = (i % (BK/4)) * 4;
            float4 v = *reinterpret_cast<const float4*>(A + (size_t)(bm+r)*lda + k0 + kq);
            As[kq+0][r] = v.x; As[kq+1][r] = v.y; As[kq+2][r] = v.z; As[kq+3][r] = v.w;
        }
        for (int i = tid; i < B4; i += THREADS) {
            int r  = i / (BK/4);
            int kq = (i % (BK/4)) * 4;
            float4 v = *reinterpret_cast<const float4*>(B + (size_t)r*ldb + k0 + kq);
            Bs[kq+0][r] = v.x; Bs[kq+1][r] = v.y; Bs[kq+2][r] = v.z; Bs[kq+3][r] = v.w;
        }
        __syncthreads();
#pragma unroll
        for (int k = 0; k < BK; k++) {
            float a[TM], b[TN];
#pragma unroll
            for (int i = 0; i < TM; i++) a[i] = As[k][ty*TM + i];
#pragma unroll
            for (int j = 0; j < TN; j++) b[j] = Bs[k][tx*TN + j];
#pragma unroll
            for (int i = 0; i < TM; i++)
#pragma unroll
                for (int j = 0; j < TN; j++)
                    acc[i][j] = fmaf(a[i], b[j], acc[i][j]);
        }
        __syncthreads();
    }
#pragma unroll
    for (int i = 0; i < TM; i++)
#pragma unroll
        for (int j = 0; j < TN; j++)
            atomicAdd(&C[(size_t)(bm + ty*TM + i)*ldc + tx*TN + j], acc[i][j]);
}

// ---------------------------------------------------------------------------
// Depthwise causal conv1d (k=4) + SiLU
// ---------------------------------------------------------------------------
__global__ void conv_silu_kernel(const float* __restrict__ cw_f, const float* __restrict__ cb_f,
                                 const float* __restrict__ cw_b, const float* __restrict__ cb_b)
{
    const int dir = blockIdx.y;
    const float* xz = g_xz[dir];
    const float* cw = dir ? cw_b : cw_f;
    const float* cb = dir ? cb_b : cb_f;
    float* xc = g_xc[dir];

    int idx = blockIdx.x * blockDim.x + threadIdx.x;
    int e = idx & (DINNER-1);
    int t = idx >> 11;
    int l = t & (SEQ-1);
    int base = t - l;

    float acc = cb[e];
#pragma unroll
    for (int k = 0; k < 4; k++) {
        int ls = l + k - 3;
        if (ls >= 0)
            acc = fmaf(cw[e*4 + k], xz[(size_t)(base + ls)*(2*DINNER) + e], acc);
    }
    acc = acc / (1.f + __expf(-acc));
    xc[idx] = acc;
}

// ---------------------------------------------------------------------------
// Selective scan + skip + gate; dA via r^k powers fast path; y fp32.
// ---------------------------------------------------------------------------
__global__ void scan_kernel(const float* __restrict__ Alog_f, const float* __restrict__ D_f,
                            const float* __restrict__ Alog_b, const float* __restrict__ D_b)
{
    const int dir = blockIdx.z;
    const int b   = blockIdx.y;
    const int e   = blockIdx.x * blockDim.x + threadIdx.x;

    const float* delta = g_delta[dir];
    const float* xc    = g_xc[dir];
    const float* dbl   = g_dbl[dir];
    const float* xz    = g_xz[dir];
    float*       yout  = g_y[dir];
    const float* Alog  = dir ? Alog_b : Alog_f;
    const float* Dp    = dir ? D_b    : D_f;

    float A[DSTATE], h[DSTATE];
    bool fast = true;
#pragma unroll
    for (int n = 0; n < DSTATE; n++) {
        A[n] = -expf(Alog[e*DSTATE + n]);
        h[n] = 0.f;
        fast = fast && (fabsf(A[n] + (float)(n+1)) < 1e-3f * (float)(n+1));
    }
    const float Dv = Dp[e];

    for (int l = 0; l < SEQ; l++) {
        const int t = b*SEQ + l;
        const float dlt = delta[(size_t)t*DINNER + e];
        const float xcv = xc[(size_t)t*DINNER + e];
        const float du  = dlt * xcv;
        const float* row = dbl + (size_t)t*96;

        float dA[DSTATE];
        if (fast) {
            const float r  = __expf(-dlt);
            const float r2 = r*r, r4 = r2*r2, r8 = r4*r4;
            dA[0]=r;        dA[1]=r2;       dA[2]=r2*r;     dA[3]=r4;
            dA[4]=r4*r;     dA[5]=r4*r2;    dA[6]=r4*dA[2]; dA[7]=r8;
            dA[8]=r8*r;     dA[9]=r8*r2;    dA[10]=r8*dA[2];dA[11]=r8*r4;
            dA[12]=r8*dA[4];dA[13]=r8*dA[5];dA[14]=r8*dA[6];dA[15]=r8*r8;
        } else {
#pragma unroll
            for (int n = 0; n < DSTATE; n++) dA[n] = __expf(dlt * A[n]);
        }

        float y0 = 0.f, y1 = 0.f, y2 = 0.f, y3 = 0.f;
#pragma unroll
        for (int n = 0; n < DSTATE; n += 4) {
            h[n+0] = fmaf(dA[n+0], h[n+0], du * row[64+n+0]);
            h[n+1] = fmaf(dA[n+1], h[n+1], du * row[64+n+1]);
            h[n+2] = fmaf(dA[n+2], h[n+2], du * row[64+n+2]);
            h[n+3] = fmaf(dA[n+3], h[n+3], du * row[64+n+3]);
            y0 = fmaf(h[n+0], row[80+n+0], y0);
            y1 = fmaf(h[n+1], row[80+n+1], y1);
            y2 = fmaf(h[n+2], row[80+n+2], y2);
            y3 = fmaf(h[n+3], row[80+n+3], y3);
        }
        float y = (y0 + y1) + (y2 + y3);

        const float zv = xz[(size_t)t*(2*DINNER) + DINNER + e];
        const float g  = zv / (1.f + __expf(-zv));
        yout[(size_t)t*DINNER + e] = (y + xcv*Dv) * g;
    }
}

// ---------------------------------------------------------------------------
extern "C" void kernel_launch(void* const* d_in, const int* in_sizes, int n_in,
                              void* d_out, int out_size)
{
    const float* x       = (const float*)d_in[0];
    const float* f_inp   = (const float*)d_in[1];
    const float* f_cw    = (const float*)d_in[2];
    const float* f_cb    = (const float*)d_in[3];
    const float* f_xp    = (const float*)d_in[4];
    const float* f_dtw   = (const float*)d_in[5];
    const float* f_dtb   = (const float*)d_in[6];
    const float* f_Alog  = (const float*)d_in[7];
    const float* f_D     = (const float*)d_in[8];
    const float* f_op    = (const float*)d_in[9];
    const float* b_inp   = (const float*)d_in[10];
    const float* b_cw    = (const float*)d_in[11];
    const float* b_cb    = (const float*)d_in[12];
    const float* b_xp    = (const float*)d_in[13];
    const float* b_dtw   = (const float*)d_in[14];
    const float* b_dtb   = (const float*)d_in[15];
    const float* b_Alog  = (const float*)d_in[16];
    const float* b_D     = (const float*)d_in[17];
    const float* b_op    = (const float*)d_in[18];
    const float* merge_w = (const float*)d_in[19];
    float* out = (float*)d_out;

    void* p;
    cudaGetSymbolAddress(&p, g_xz);    float* xz0 = (float*)p; float* xz1 = xz0 + PLANE_XZ;
    cudaGetSymbolAddress(&p, g_dbl);   float* db0 = (float*)p; float* db1 = db0 + PLANE_DBL;
    cudaGetSymbolAddress(&p, g_delta); float* dl0 = (float*)p; float* dl1 = dl0 + PLANE_E;
    cudaGetSymbolAddress(&p, g_xc);    float* xc0 = (float*)p; float* xc1 = xc0 + PLANE_E;
    cudaGetSymbolAddress(&p, g_y);     float* y0f = (float*)p; float* y1f = y0f + PLANE_E;
    cudaGetSymbolAddress(&p, g_ocatf); float* ocf = (float*)p;

    int8_t *qx, *qw0, *qw1, *qo0, *qo1, *qmg, *qy0, *qy1, *qoc;
    float *sx, *sw0, *sw1, *so0, *so1, *smg, *sy0, *sy1, *soc;
    cudaGetSymbolAddress(&p, q_x);    qx  = (int8_t*)p;
    cudaGetSymbolAddress(&p, q_win);  qw0 = (int8_t*)p; qw1 = qw0 + (size_t)2*DINNER*2*DMODEL;
    cudaGetSymbolAddress(&p, q_wop);  qo0 = (int8_t*)p; qo1 = qo0 + (size_t)DMODEL*2*DINNER;
    cudaGetSymbolAddress(&p, q_wmg);  qmg = (int8_t*)p;
    cudaGetSymbolAddress(&p, q_y);    qy0 = (int8_t*)p; qy1 = qy0 + (size_t)TOK*2*DINNER;
    cudaGetSymbolAddress(&p, q_ocat); qoc = (int8_t*)p;
    cudaGetSymbolAddress(&p, s_x);    sx  = (float*)p;
    cudaGetSymbolAddress(&p, s_win);  sw0 = (float*)p; sw1 = sw0 + 2*DINNER;
    cudaGetSymbolAddress(&p, s_wop);  so0 = (float*)p; so1 = so0 + DMODEL;
    cudaGetSymbolAddress(&p, s_wmg);  smg = (float*)p;
    cudaGetSymbolAddress(&p, s_y);    sy0 = (float*)p; sy1 = sy0 + TOK;
    cudaGetSymbolAddress(&p, s_ocat); soc = (float*)p;

    __half *wdt0, *wdt1, *dth0, *dth1;
    cudaGetSymbolAddress(&p, g_wdt);  wdt0 = (__half*)p; wdt1 = wdt0 + (size_t)DINNER*DTRANK;
    cudaGetSymbolAddress(&p, g_dthl); dth0 = (__half*)p; dth1 = dth0 + (size_t)TOK*2*DTRANK;

    cudaFuncSetAttribute((const void*)gemm_i8, cudaFuncAttributeMaxDynamicSharedMemorySize, GSMEM);
    cudaFuncSetAttribute((const void*)gemm_f16<true>, cudaFuncAttributeMaxDynamicSharedMemorySize, GSMEM);

    // memset (NOT counted by ncu) + exactly 5 kernels, so the in_proj GEMM
    // is profiled by ncu -s 5 -c 1.
    cudaMemsetAsync(db0, 0, 2 * PLANE_DBL * sizeof(float));
    quant_rows<<<TOK, 256>>>(x, qx, sx, DMODEL);                 // 1
    quant_rows<<<2*DINNER, 256>>>(f_inp, qw0, sw0, DMODEL);      // 2
    quant_rows<<<2*DINNER, 256>>>(b_inp, qw1, sw1, DMODEL);      // 3
    quant_rows<<<DMODEL, 256>>>(f_op, qo0, so0, DINNER);         // 4
    quant_rows<<<DMODEL, 256>>>(b_op, qo1, so1, DINNER);         // 5

    // 6) in_proj both dirs: xz = X @ in_proj^T  (M=2048, N=4096, K=1024)
    {
        dim3 grid(4096/128, TOK/128, 2);
        gemm_i8<<<grid,256,GSMEM>>>(qx, qx, qw0, qw1, sx, sx, sw0, sw1,
                                    xz0, xz1, 2*DINNER, DMODEL,
                                    /*flipa*/0, 1, /*flipc*/0, 0);
    }

    // remaining quant/converts
    quant_rows<<<DMODEL, 256>>>(merge_w, qmg, smg, 2*DMODEL);
    cvt_w<<<((size_t)DINNER*DTRANK)/1024, 256>>>(f_dtw, wdt0);
    cvt_w<<<((size_t)DINNER*DTRANK)/1024, 256>>>(b_dtw, wdt1);

    // depthwise conv + SiLU (both dirs)
    {
        dim3 grid((TOK*DINNER)/256, 2);
        conv_silu_kernel<<<grid,256>>>(f_cw, f_cb, b_cw, b_cb);
    }

    // x_proj both dirs: dbl = xc @ x_proj^T  (M=2048, N=96, K=2048), split-K=8
    {
        dim3 grid(8, TOK/32, 2);
        gemm_nt_atomic<32,96,16,2,6><<<grid,256>>>(
            xc0, f_xp, db0, xc1, b_xp, db1, DINNER, DINNER, 96, DINNER/8);
    }

    // split dt columns of dbl (both dirs, fp16 hi/lo)
    {
        dim3 grid((TOK*DTRANK)/1024, 2);
        cvt_dt<<<grid, 256>>>(db0, dth0, db1, dth1);
    }

    // dt projection + fused bias/softplus, both dirs (fp16, K=64)
    {
        dim3 grid(DINNER/128, TOK/128, 2);
        gemm_f16<true><<<grid,256,GSMEM>>>(
            dth0, dth1, wdt0, wdt1, dl0, dl1, DINNER, DTRANK, f_dtb, b_dtb);
    }

    // selective scan + skip + gate -> y fp32
    {
        dim3 grid(DINNER/128, BSZ, 2);
        scan_kernel<<<grid,128>>>(f_Alog, f_D, b_Alog, b_D);
    }

    // quantize y (both dirs)
    quant_rows<<<TOK, 256>>>(y0f, qy0, sy0, DINNER);
    quant_rows<<<TOK, 256>>>(y1f, qy1, sy1, DINNER);

    // out_proj both dirs -> ocatf fp32 (bwd rows flipped into cols 1024..2047)
    {
        dim3 grid(DMODEL/128, TOK/128, 2);
        gemm_i8<<<grid,256,GSMEM>>>(qy0, qy1, qo0, qo1, sy0, sy1, so0, so1,
                                    ocf, ocf + DMODEL, 2*DMODEL, DINNER,
                                    /*flipa*/0, 0, /*flipc*/0, 1);
    }

    // quantize ocat rows (K = 2048)
    quant_rows<<<TOK, 256>>>(ocf, qoc, soc, 2*DMODEL);

    // merge: out = [f | flip(b)] @ merge_w^T  (M=2048, N=1024, K=2048)
    {
        dim3 grid(DMODEL/128, TOK/128, 1);
        gemm_i8<<<grid,256,GSMEM>>>(qoc, qoc, qmg, qmg, soc, soc, smg, smg,
                                    out, out, DMODEL, 2*DMODEL, 0, 0, 0, 0);
    }
}

// round 15
// speedup vs baseline: 1.7768x; 1.7768x over previous
#include <cuda_runtime.h>
#include <cuda_fp16.h>
#include <cstdint>

// ===========================================================================
// BiMamba via mma.sync fp16 1-product GEMMs (both operands rounded to fp16,
// fp32 accumulate). Error budget: ~6e-4 << 1e-3 gate.
// 3-stage cp.async pipeline, dual-direction launches via blockIdx.z.
// B=2, L=1024, D_MODEL=1024, D_INNER=2048, DT_RANK=64, D_STATE=16
// ===========================================================================

#define BSZ     2
#define SEQ     1024
#define DMODEL  1024
#define DINNER  2048
#define DTRANK  64
#define DSTATE  16
#define TOK     (BSZ*SEQ)

#define PLANE_XZ   ((size_t)TOK * (2*DINNER))
#define PLANE_E    ((size_t)TOK * DINNER)
#define PLANE_DBL  ((size_t)TOK * 96)

// fp32 intermediates
__device__ float g_xz[2][PLANE_XZ];     // xi | z per direction
__device__ float g_xc[2][PLANE_E];      // conv+silu output
__device__ float g_dbl[2][PLANE_DBL];   // dt(64) | B(16) | C(16)
__device__ float g_delta[2][PLANE_E];   // softplus(dt@dt_w + b)

// fp16 operands (plain)
__device__ __half g_xh  [(size_t)TOK * DMODEL];
__device__ __half g_win [2][(size_t)2*DINNER * DMODEL];
__device__ __half g_wdt [2][(size_t)DINNER * DTRANK];
__device__ __half g_wop [2][(size_t)DMODEL * DINNER];
__device__ __half g_wmg [(size_t)DMODEL * (2*DMODEL)];
__device__ __half g_dth [2][(size_t)TOK * DTRANK];
__device__ __half g_yh  [2][(size_t)TOK * DINNER];
__device__ __half g_ocat[(size_t)TOK * (2*DMODEL)];   // [f | flip(b)]

// ---------------------------------------------------------------------------
// asm helpers
// ---------------------------------------------------------------------------
__device__ __forceinline__ void ldsm_x4(uint32_t* r, uint32_t addr) {
    asm volatile("ldmatrix.sync.aligned.m8n8.x4.shared.b16 {%0,%1,%2,%3}, [%4];"
        : "=r"(r[0]), "=r"(r[1]), "=r"(r[2]), "=r"(r[3]) : "r"(addr));
}
__device__ __forceinline__ void mma16816(float* c, const uint32_t* a, const uint32_t* b) {
    asm volatile(
        "mma.sync.aligned.m16n8k16.row.col.f32.f16.f16.f32 "
        "{%0,%1,%2,%3}, {%4,%5,%6,%7}, {%8,%9}, {%0,%1,%2,%3};"
        : "+f"(c[0]), "+f"(c[1]), "+f"(c[2]), "+f"(c[3])
        : "r"(a[0]), "r"(a[1]), "r"(a[2]), "r"(a[3]), "r"(b[0]), "r"(b[1]));
}
#define CP_ASYNC16(dst, src) \
    asm volatile("cp.async.cg.shared.global [%0], [%1], 16;" :: "r"(dst), "l"(src))
#define CP_COMMIT() asm volatile("cp.async.commit_group;" ::: "memory")
#define CP_WAIT1()  asm volatile("cp.async.wait_group 1;" ::: "memory")
#define CP_WAIT0()  asm volatile("cp.async.wait_group 0;" ::: "memory")

#define GSMEM (3*32768)

// ---------------------------------------------------------------------------
// 1-product fp16 GEMM: C[M,N] = A[M,:K] * B[N,:K].
// Block tile 128x128, BK=64, 3-stage cp.async ring, 8 warps (2x4), 2 CTAs/SM.
// ---------------------------------------------------------------------------
template<bool SOFTPLUS, bool OUTH>
__global__ __launch_bounds__(256, 2)
void gemm_f16(const __half* __restrict__ A0, const __half* __restrict__ A1,
              const __half* __restrict__ B0, const __half* __restrict__ B1,
              float* C0, float* C1, int ldc,
              __half* Cb0, __half* Cb1, int ldcb,
              int K, const float* bias0, const float* bias1,
              int flipa0, int flipa1, int flipc0, int flipc1)
{
    extern __shared__ __align__(128) char smem_raw[];
    const uint32_t sbase = (uint32_t)__cvta_generic_to_shared(smem_raw);

    const int z = blockIdx.z;
    const __half* A = z ? A1 : A0;
    const __half* B = z ? B1 : B0;
    float* C = z ? C1 : C0;
    __half* Cb = z ? Cb1 : Cb0;
    const float* bias = z ? bias1 : bias0;
    const int flipa = z ? flipa1 : flipa0;
    const int flipc = z ? flipc1 : flipc0;

    const int tid = threadIdx.x;
    const int wid = tid >> 5;
    const int lid = tid & 31;
    const int bm = blockIdx.y * 128;
    const int bn = blockIdx.x * 128;

    const int wm = wid >> 2;
    const int wn = wid & 3;
    const int mbase = wm * 64;
    const int nbase = wn * 32;
    const int qrow = lid & 15;
    const int qc16 = lid >> 4;

    const int nv = K >> 6;

    float acc[4][4][4];
#pragma unroll
    for (int f = 0; f < 4; f++)
#pragma unroll
        for (int g = 0; g < 4; g++)
#pragma unroll
            for (int e = 0; e < 4; e++) acc[f][g][e] = 0.f;

    auto sA = [&](int st) -> uint32_t { return sbase + (uint32_t)st * 32768u; };
    auto sB = [&](int st) -> uint32_t { return sbase + (uint32_t)st * 32768u + 16384u; };

    auto load_stage = [&](int v, int st) {
        const int koff = v << 6;
        uint32_t da = sA(st), db = sB(st);
#pragma unroll
        for (int i = 0; i < 4; i++) {
            int ch  = tid + (i << 8);
            int r   = ch >> 3;
            int c16 = ch & 7;
            uint32_t sw = (uint32_t)((c16 ^ (r & 7)) << 4) + (uint32_t)(r << 7);
            int gm = bm + r;
            int am = flipa ? (gm ^ (SEQ-1)) : gm;
            CP_ASYNC16(da + sw, A + (size_t)am * K + koff + (c16 << 3));
            CP_ASYNC16(db + sw, B + (size_t)(bn + r) * K + koff + (c16 << 3));
        }
    };

    auto compute_stage = [&](int st) {
        uint32_t sa = sA(st), sb = sB(st);
#pragma unroll
        for (int s = 0; s < 4; s++) {
            uint32_t bq[2][4];
#pragma unroll
            for (int g2 = 0; g2 < 2; g2++) {
                int r = nbase + g2*16 + qrow;
                int c = (s << 1) + qc16;
                ldsm_x4(bq[g2], sb + (uint32_t)(r << 7) + (uint32_t)((c ^ (r & 7)) << 4));
            }
#pragma unroll
            for (int f = 0; f < 4; f++) {
                int r = mbase + f*16 + qrow;
                int c = (s << 1) + qc16;
                uint32_t afr[4];
                ldsm_x4(afr, sa + (uint32_t)(r << 7) + (uint32_t)((c ^ (r & 7)) << 4));
#pragma unroll
                for (int g = 0; g < 4; g++) {
                    uint32_t bfr[2] = { bq[g >> 1][g & 1], bq[g >> 1][(g & 1) + 2] };
                    mma16816(acc[f][g], afr, bfr);
                }
            }
        }
    };

    load_stage(0, 0); CP_COMMIT();
    if (nv > 1) { load_stage(1, 1); CP_COMMIT(); }

    for (int v = 0; v < nv; v++) {
        int st = v % 3;
        if (v < nv - 1) CP_WAIT1(); else CP_WAIT0();
        __syncthreads();
        compute_stage(st);
        int vn = v + 2;
        if (vn < nv) { load_stage(vn, vn % 3); CP_COMMIT(); }
    }

    // ---- epilogue ----
    const int crow = lid >> 2;
    const int ccol = (lid & 3) * 2;
#pragma unroll
    for (int f = 0; f < 4; f++) {
        int m0 = bm + mbase + f*16 + crow;
        int m1 = m0 + 8;
        int gm0 = flipc ? (m0 ^ (SEQ-1)) : m0;
        int gm1 = flipc ? (m1 ^ (SEQ-1)) : m1;
#pragma unroll
        for (int g = 0; g < 4; g++) {
            int n = bn + nbase + g*8 + ccol;
            float v0 = acc[f][g][0], v1 = acc[f][g][1];
            float v2 = acc[f][g][2], v3 = acc[f][g][3];
            if (SOFTPLUS) {
                float b0 = bias[n], b1 = bias[n+1];
                float x0 = v0 + b0, x1 = v1 + b1, x2 = v2 + b0, x3 = v3 + b1;
                v0 = (x0 > 20.f) ? x0 : log1pf(__expf(x0));
                v1 = (x1 > 20.f) ? x1 : log1pf(__expf(x1));
                v2 = (x2 > 20.f) ? x2 : log1pf(__expf(x2));
                v3 = (x3 > 20.f) ? x3 : log1pf(__expf(x3));
            }
            if (OUTH) {
                *reinterpret_cast<__half2*>(Cb + (size_t)gm0*ldcb + n) =
                    __halves2half2(__float2half_rn(v0), __float2half_rn(v1));
                *reinterpret_cast<__half2*>(Cb + (size_t)gm1*ldcb + n) =
                    __halves2half2(__float2half_rn(v2), __float2half_rn(v3));
            } else {
                *reinterpret_cast<float2*>(C + (size_t)gm0*ldc + n) = make_float2(v0, v1);
                *reinterpret_cast<float2*>(C + (size_t)gm1*ldc + n) = make_float2(v2, v3);
            }
        }
    }
}

// ---------------------------------------------------------------------------
// fp32 -> plain fp16 (flat)
// ---------------------------------------------------------------------------
__global__ void cvt_w(const float* __restrict__ in, __half* __restrict__ out)
{
    int idx = (blockIdx.x * blockDim.x + threadIdx.x) << 2;
    float4 v = *reinterpret_cast<const float4*>(in + idx);
    *reinterpret_cast<__half2*>(out + idx)     = __halves2half2(__float2half_rn(v.x), __float2half_rn(v.y));
    *reinterpret_cast<__half2*>(out + idx + 2) = __halves2half2(__float2half_rn(v.z), __float2half_rn(v.w));
}

// dbl (stride 96, cols 0..63) -> packed [TOK][64] fp16; both dirs (grid.y)
__global__ void cvt_dt(const float* __restrict__ in0, __half* __restrict__ out0,
                       const float* __restrict__ in1, __half* __restrict__ out1)
{
    const float* in = blockIdx.y ? in1 : in0;
    __half* out = blockIdx.y ? out1 : out0;
    int idx = (blockIdx.x * blockDim.x + threadIdx.x) << 2;   // over TOK*64
    int row = idx >> 6;
    int col = idx & 63;
    float4 v = *reinterpret_cast<const float4*>(in + (size_t)row * 96 + col);
    size_t o = (size_t)row * 64 + col;
    *reinterpret_cast<__half2*>(out + o)     = __halves2half2(__float2half_rn(v.x), __float2half_rn(v.y));
    *reinterpret_cast<__half2*>(out + o + 2) = __halves2half2(__float2half_rn(v.z), __float2half_rn(v.w));
}

// ---------------------------------------------------------------------------
// Small split-K fp32 GEMM with atomicAdd epilogue (x_proj), both dirs (grid.z)
// ---------------------------------------------------------------------------
template<int BM,int BN,int BK,int TM,int TN>
__global__ __launch_bounds__((BM/TM)*(BN/TN))
void gemm_nt_atomic(const float* __restrict__ A0, const float* __restrict__ B0, float* C0,
                    const float* __restrict__ A1, const float* __restrict__ B1, float* C1,
                    int lda, int ldb, int ldc, int kslab)
{
    constexpr int THREADS = (BM/TM)*(BN/TN);
    __shared__ float As[BK][BM];
    __shared__ float Bs[BK][BN];
    const float* A = blockIdx.z ? A1 : A0;
    const float* B = blockIdx.z ? B1 : B0;
    float* C = blockIdx.z ? C1 : C0;
    const int tid = threadIdx.x;
    const int bm  = blockIdx.y * BM;
    const int k_lo = blockIdx.x * kslab;
    const int tx = tid % (BN/TN);
    const int ty = tid / (BN/TN);

    float acc[TM][TN];
#pragma unroll
    for (int i = 0; i < TM; i++)
#pragma unroll
        for (int j = 0; j < TN; j++) acc[i][j] = 0.f;

    constexpr int A4 = BM*BK/4;
    constexpr int B4 = BN*BK/4;
    for (int k0 = k_lo; k0 < k_lo + kslab; k0 += BK) {
        for (int i = tid; i < A4; i += THREADS) {
            int r  = i / (BK/4);
            int kq = (i % (BK/4)) * 4;
            float4 v = *reinterpret_cast<const float4*>(A + (size_t)(bm+r)*lda + k0 + kq);
            As[kq+0][r] = v.x; As[kq+1][r] = v.y; As[kq+2][r] = v.z; As[kq+3][r] = v.w;
        }
        for (int i = tid; i < B4; i += THREADS) {
            int r  = i / (BK/4);
            int kq = (i % (BK/4)) * 4;
            float4 v = *reinterpret_cast<const float4*>(B + (size_t)r*ldb + k0 + kq);
            Bs[kq+0][r] = v.x; Bs[kq+1][r] = v.y; Bs[kq+2][r] = v.z; Bs[kq+3][r] = v.w;
        }
        __syncthreads();
#pragma unroll
        for (int k = 0; k < BK; k++) {
            float a[TM], b[TN];
#pragma unroll
            for (int i = 0; i < TM; i++) a[i] = As[k][ty*TM + i];
#pragma unroll
            for (int j = 0; j < TN; j++) b[j] = Bs[k][tx*TN + j];
#pragma unroll
            for (int i = 0; i < TM; i++)
#pragma unroll
                for (int j = 0; j < TN; j++)
                    acc[i][j] = fmaf(a[i], b[j], acc[i][j]);
        }
        __syncthreads();
    }
#pragma unroll
    for (int i = 0; i < TM; i++)
#pragma unroll
        for (int j = 0; j < TN; j++)
            atomicAdd(&C[(size_t)(bm + ty*TM + i)*ldc + tx*TN + j], acc[i][j]);
}

// ---------------------------------------------------------------------------
// Depthwise causal conv1d (k=4) + SiLU
// ---------------------------------------------------------------------------
__global__ void conv_silu_kernel(const float* __restrict__ cw_f, const float* __restrict__ cb_f,
                                 const float* __restrict__ cw_b, const float* __restrict__ cb_b)
{
    const int dir = blockIdx.y;
    const float* xz = g_xz[dir];
    const float* cw = dir ? cw_b : cw_f;
    const float* cb = dir ? cb_b : cb_f;
    float* xc = g_xc[dir];

    int idx = blockIdx.x * blockDim.x + threadIdx.x;
    int e = idx & (DINNER-1);
    int t = idx >> 11;
    int l = t & (SEQ-1);
    int base = t - l;

    float acc = cb[e];
#pragma unroll
    for (int k = 0; k < 4; k++) {
        int ls = l + k - 3;
        if (ls >= 0)
            acc = fmaf(cw[e*4 + k], xz[(size_t)(base + ls)*(2*DINNER) + e], acc);
    }
    acc = acc / (1.f + __expf(-acc));
    xc[idx] = acc;
}

// ---------------------------------------------------------------------------
// Selective scan + skip + gate; dA via r^k powers fast path; y -> fp16.
// ---------------------------------------------------------------------------
__global__ void scan_kernel(const float* __restrict__ Alog_f, const float* __restrict__ D_f,
                            const float* __restrict__ Alog_b, const float* __restrict__ D_b)
{
    const int dir = blockIdx.z;
    const int b   = blockIdx.y;
    const int e   = blockIdx.x * blockDim.x + threadIdx.x;

    const float* delta = g_delta[dir];
    const float* xc    = g_xc[dir];
    const float* dbl   = g_dbl[dir];
    const float* xz    = g_xz[dir];
    __half*      yh    = g_yh[dir];
    const float* Alog  = dir ? Alog_b : Alog_f;
    const float* Dp    = dir ? D_b    : D_f;

    float A[DSTATE], h[DSTATE];
    bool fast = true;
#pragma unroll
    for (int n = 0; n < DSTATE; n++) {
        A[n] = -expf(Alog[e*DSTATE + n]);
        h[n] = 0.f;
        fast = fast && (fabsf(A[n] + (float)(n+1)) < 1e-3f * (float)(n+1));
    }
    const float Dv = Dp[e];

    for (int l = 0; l < SEQ; l++) {
        const int t = b*SEQ + l;
        const float dlt = delta[(size_t)t*DINNER + e];
        const float xcv = xc[(size_t)t*DINNER + e];
        const float du  = dlt * xcv;
        const float* row = dbl + (size_t)t*96;

        float dA[DSTATE];
        if (fast) {
            const float r  = __expf(-dlt);
            const float r2 = r*r, r4 = r2*r2, r8 = r4*r4;
            dA[0]=r;        dA[1]=r2;       dA[2]=r2*r;     dA[3]=r4;
            dA[4]=r4*r;     dA[5]=r4*r2;    dA[6]=r4*dA[2]; dA[7]=r8;
            dA[8]=r8*r;     dA[9]=r8*r2;    dA[10]=r8*dA[2];dA[11]=r8*r4;
            dA[12]=r8*dA[4];dA[13]=r8*dA[5];dA[14]=r8*dA[6];dA[15]=r8*r8;
        } else {
#pragma unroll
            for (int n = 0; n < DSTATE; n++) dA[n] = __expf(dlt * A[n]);
        }

        float y0 = 0.f, y1 = 0.f, y2 = 0.f, y3 = 0.f;
#pragma unroll
        for (int n = 0; n < DSTATE; n += 4) {
            h[n+0] = fmaf(dA[n+0], h[n+0], du * row[64+n+0]);
            h[n+1] = fmaf(dA[n+1], h[n+1], du * row[64+n+1]);
            h[n+2] = fmaf(dA[n+2], h[n+2], du * row[64+n+2]);
            h[n+3] = fmaf(dA[n+3], h[n+3], du * row[64+n+3]);
            y0 = fmaf(h[n+0], row[80+n+0], y0);
            y1 = fmaf(h[n+1], row[80+n+1], y1);
            y2 = fmaf(h[n+2], row[80+n+2], y2);
            y3 = fmaf(h[n+3], row[80+n+3], y3);
        }
        float y = (y0 + y1) + (y2 + y3);

        const float zv = xz[(size_t)t*(2*DINNER) + DINNER + e];
        const float g  = zv / (1.f + __expf(-zv));
        float yv = (y + xcv*Dv) * g;
        yh[(size_t)t*DINNER + e] = __float2half_rn(yv);
    }
}

// ---------------------------------------------------------------------------
extern "C" void kernel_launch(void* const* d_in, const int* in_sizes, int n_in,
                              void* d_out, int out_size)
{
    const float* x       = (const float*)d_in[0];
    const float* f_inp   = (const float*)d_in[1];
    const float* f_cw    = (const float*)d_in[2];
    const float* f_cb    = (const float*)d_in[3];
    const float* f_xp    = (const float*)d_in[4];
    const float* f_dtw   = (const float*)d_in[5];
    const float* f_dtb   = (const float*)d_in[6];
    const float* f_Alog  = (const float*)d_in[7];
    const float* f_D     = (const float*)d_in[8];
    const float* f_op    = (const float*)d_in[9];
    const float* b_inp   = (const float*)d_in[10];
    const float* b_cw    = (const float*)d_in[11];
    const float* b_cb    = (const float*)d_in[12];
    const float* b_xp    = (const float*)d_in[13];
    const float* b_dtw   = (const float*)d_in[14];
    const float* b_dtb   = (const float*)d_in[15];
    const float* b_Alog  = (const float*)d_in[16];
    const float* b_D     = (const float*)d_in[17];
    const float* b_op    = (const float*)d_in[18];
    const float* merge_w = (const float*)d_in[19];
    float* out = (float*)d_out;

    void* p;
    cudaGetSymbolAddress(&p, g_xz);    float* xz0 = (float*)p; float* xz1 = xz0 + PLANE_XZ;
    cudaGetSymbolAddress(&p, g_dbl);   float* db0 = (float*)p; float* db1 = db0 + PLANE_DBL;
    cudaGetSymbolAddress(&p, g_delta); float* dl0 = (float*)p; float* dl1 = dl0 + PLANE_E;
    cudaGetSymbolAddress(&p, g_xc);    float* xc0 = (float*)p; float* xc1 = xc0 + PLANE_E;

    __half *xh, *win0, *win1, *wdt0, *wdt1, *wop0, *wop1, *wmg,
           *dt0, *dt1, *yh0, *yh1, *ocat;
    cudaGetSymbolAddress(&p, g_xh);   xh   = (__half*)p;
    cudaGetSymbolAddress(&p, g_win);  win0 = (__half*)p; win1 = win0 + (size_t)2*DINNER*DMODEL;
    cudaGetSymbolAddress(&p, g_wdt);  wdt0 = (__half*)p; wdt1 = wdt0 + (size_t)DINNER*DTRANK;
    cudaGetSymbolAddress(&p, g_wop);  wop0 = (__half*)p; wop1 = wop0 + (size_t)DMODEL*DINNER;
    cudaGetSymbolAddress(&p, g_wmg);  wmg  = (__half*)p;
    cudaGetSymbolAddress(&p, g_dth);  dt0  = (__half*)p; dt1  = dt0  + (size_t)TOK*DTRANK;
    cudaGetSymbolAddress(&p, g_yh);   yh0  = (__half*)p; yh1  = yh0  + (size_t)TOK*DINNER;
    cudaGetSymbolAddress(&p, g_ocat); ocat = (__half*)p;

    cudaFuncSetAttribute((const void*)gemm_f16<false,false>, cudaFuncAttributeMaxDynamicSharedMemorySize, GSMEM);
    cudaFuncSetAttribute((const void*)gemm_f16<true ,false>, cudaFuncAttributeMaxDynamicSharedMemorySize, GSMEM);
    cudaFuncSetAttribute((const void*)gemm_f16<false,true >, cudaFuncAttributeMaxDynamicSharedMemorySize, GSMEM);

    // ncu captures the 5th launch counting the memset -> the in_proj GEMM.
    cudaMemsetAsync(db0, 0, 2 * PLANE_DBL * sizeof(float));                      // 1
    cvt_w<<<(TOK*DMODEL)/1024, 256>>>(x, xh);                                    // 2
    cvt_w<<<((size_t)2*DINNER*DMODEL)/1024, 256>>>(f_inp, win0);                 // 3
    cvt_w<<<((size_t)2*DINNER*DMODEL)/1024, 256>>>(b_inp, win1);                 // 4

    // 5) in_proj both dirs: xz = X @ in_proj^T  (M=2048, N=4096, K=1024)
    {
        dim3 grid(4096/128, TOK/128, 2);
        gemm_f16<false,false><<<grid,256,GSMEM>>>(
            xh, xh, win0, win1, xz0, xz1, 2*DINNER,
            nullptr, nullptr, 0, DMODEL, nullptr, nullptr,
            /*flipa*/0, 1, /*flipc*/0, 0);
    }

    // remaining weight converts
    cvt_w<<<((size_t)DINNER*DTRANK)/1024, 256>>>(f_dtw, wdt0);
    cvt_w<<<((size_t)DINNER*DTRANK)/1024, 256>>>(b_dtw, wdt1);
    cvt_w<<<((size_t)DMODEL*DINNER)/1024, 256>>>(f_op, wop0);
    cvt_w<<<((size_t)DMODEL*DINNER)/1024, 256>>>(b_op, wop1);
    cvt_w<<<((size_t)DMODEL*2*DMODEL)/1024, 256>>>(merge_w, wmg);

    // depthwise conv + SiLU (both dirs)
    {
        dim3 grid((TOK*DINNER)/256, 2);
        conv_silu_kernel<<<grid,256>>>(f_cw, f_cb, b_cw, b_cb);
    }

    // x_proj both dirs: dbl = xc @ x_proj^T  (M=2048, N=96, K=2048), split-K=8
    {
        dim3 grid(8, TOK/32, 2);
        gemm_nt_atomic<32,96,16,2,6><<<grid,256>>>(
            xc0, f_xp, db0, xc1, b_xp, db1, DINNER, DINNER, 96, DINNER/8);
    }

    // pack dt columns of dbl (both dirs, plain fp16)
    {
        dim3 grid((TOK*DTRANK)/1024, 2);
        cvt_dt<<<grid, 256>>>(db0, dt0, db1, dt1);
    }

    // dt projection + fused bias/softplus, both dirs (M=2048, N=2048, K=64)
    {
        dim3 grid(DINNER/128, TOK/128, 2);
        gemm_f16<true,false><<<grid,256,GSMEM>>>(
            dt0, dt1, wdt0, wdt1, dl0, dl1, DINNER,
            nullptr, nullptr, 0, DTRANK, f_dtb, b_dtb, 0, 0, 0, 0);
    }

    // selective scan + skip + gate -> yh (fp16)
    {
        dim3 grid(DINNER/128, BSZ, 2);
        scan_kernel<<<grid,128>>>(f_Alog, f_D, b_Alog, b_D);
    }

    // out_proj both dirs (M=2048, N=1024, K=2048) -> ocat fp16, bwd flipped
    {
        dim3 grid(DMODEL/128, TOK/128, 2);
        gemm_f16<false,true><<<grid,256,GSMEM>>>(
            yh0, yh1, wop0, wop1, nullptr, nullptr, 0,
            ocat, ocat + DMODEL, 2*DMODEL, DINNER,
            nullptr, nullptr, 0, 0, /*flipc*/0, 1);
    }

    // merge: out = [f | flip(b)] @ merge_w^T  (M=2048, N=1024, K=2048)
    {
        dim3 grid(DMODEL/128, TOK/128, 1);
        gemm_f16<false,false><<<grid,256,GSMEM>>>(
            ocat, ocat, wmg, wmg, out, out, DMODEL,
            nullptr, nullptr, 0, 2*DMODEL, nullptr, nullptr, 0, 0, 0, 0);
    }
}